// round 15
// baseline (speedup 1.0000x reference)
#include <cuda_runtime.h>
#include <cuda_fp16.h>
#include <math.h>

#define BB 8
#define NPTS 2048
#define NPAIR 1024
#define NTHREADS 512
#define ROWS_PER_CTA 128          // warm: 16 warps * 8 rows
#define CHUNKS 16                 // warm/dist grid.x
#define NCHUNK 32                 // j-chunks of 64 points

// persistent kernel
#define PTHREADS 1024             // 32 warps * 4 rows = 128 rows/CTA
#define NCTA 128                  // 16 x-chunks * 8 batches, all resident
#define PSTEPS 97                 // 48*(f,g) + final f

// eps = 0.005
#define KLOG 288.53900817779268f          // log2(e)/eps
#define INV2K 0.0017328679513998633f      // 1/(2*KLOG)
#define EPSLN2 0.0034657359027997266f     // eps*ln2
#define ACONST (-0.038123094930796993f)   // eps*log(1/N)
#define SKIP_THR (-30.0f)

typedef unsigned long long u64;

__device__ __forceinline__ float ex2f(float x) {
    float r;
    asm("ex2.approx.ftz.f32 %0, %1;" : "=f"(r) : "f"(x));
    return r;
}
__device__ __forceinline__ u64 pack2(float lo, float hi) {
    u64 r; asm("mov.b64 %0, {%1, %2};" : "=l"(r) : "f"(lo), "f"(hi)); return r;
}
__device__ __forceinline__ void unpack2(u64 v, float& lo, float& hi) {
    asm("mov.b64 {%0, %1}, %2;" : "=f"(lo), "=f"(hi) : "l"(v));
}
__device__ __forceinline__ u64 fma2(u64 a, u64 b, u64 c) {
    u64 r; asm("fma.rn.f32x2 %0, %1, %2, %3;" : "=l"(r) : "l"(a), "l"(b), "l"(c)); return r;
}
__device__ __forceinline__ u64 add2(u64 a, u64 b) {
    u64 r; asm("add.rn.f32x2 %0, %1, %2;" : "=l"(r) : "l"(a), "l"(b)); return r;
}

// Persistent scratch
__device__ float  g_p1[BB * NPTS * 3];
__device__ float  g_p2[BB * NPTS * 3];
__device__ float4 g_lo1[BB * NCHUNK], g_hi1[BB * NCHUNK];
__device__ float4 g_lo2[BB * NCHUNK], g_hi2[BB * NCHUNK];
__device__ float  g_f[BB * NPTS];
__device__ float  g_g[BB * NPTS];
__device__ float  g_mf[BB * NPTS];
__device__ float  g_mg[BB * NPTS];
__device__ float  g_partial[BB * CHUNKS];

// grid barrier state (generation counter: no reset needed across graph replays)
__device__ int      g_bar_cnt;
__device__ unsigned g_bar_gen;

__device__ __forceinline__ void grid_bar() {
    __syncthreads();
    if (threadIdx.x == 0) {
        __threadfence();   // release: make this CTA's writes visible
        unsigned gen;
        asm volatile("ld.volatile.global.u32 %0, [%1];" : "=r"(gen) : "l"(&g_bar_gen));
        if (atomicAdd(&g_bar_cnt, 1) == NCTA - 1) {
            asm volatile("st.volatile.global.u32 [%0], %1;" :: "l"(&g_bar_cnt), "r"(0));
            __threadfence();
            atomicAdd(&g_bar_gen, 1u);
        } else {
            unsigned cur;
            do {
                asm volatile("ld.volatile.global.u32 %0, [%1];" : "=r"(cur) : "l"(&g_bar_gen));
            } while (cur == gen);
        }
        __threadfence();   // acquire: see other CTAs' writes
    }
    __syncthreads();
}

__global__ void init_kernel() {
    int i = blockIdx.x * blockDim.x + threadIdx.x;
    if (i < BB * NPTS) g_g[i] = 0.0f;
}

__device__ __forceinline__ unsigned expand_bits(unsigned v) {
    v &= 0x3FFu;
    v = (v | (v << 16)) & 0x030000FFu;
    v = (v | (v << 8))  & 0x0300F00Fu;
    v = (v | (v << 4))  & 0x030C30C3u;
    v = (v | (v << 2))  & 0x09249249u;
    return v;
}

// One CTA per batch: Morton bitonic sort + per-chunk AABB.
__global__ __launch_bounds__(NTHREADS, 1)
void sort_kernel(const float* __restrict__ pts, int side)
{
    __shared__ unsigned key[NPTS];
    __shared__ int      idx[NPTS];
    const int b = blockIdx.x, tid = threadIdx.x;
    const float* p = pts + b * NPTS * 3;

    for (int j = tid; j < NPTS; j += NTHREADS) {
        float x = p[3*j], y = p[3*j+1], z = p[3*j+2];
        unsigned qx = (unsigned)fminf(fmaxf(x * 1024.0f, 0.0f), 1023.0f);
        unsigned qy = (unsigned)fminf(fmaxf(y * 1024.0f, 0.0f), 1023.0f);
        unsigned qz = (unsigned)fminf(fmaxf(z * 1024.0f, 0.0f), 1023.0f);
        key[j] = expand_bits(qx) | (expand_bits(qy) << 1) | (expand_bits(qz) << 2);
        idx[j] = j;
    }
    __syncthreads();

    for (int k2 = 2; k2 <= NPTS; k2 <<= 1) {
        for (int j2 = k2 >> 1; j2 > 0; j2 >>= 1) {
            for (int i = tid; i < NPTS; i += NTHREADS) {
                int l = i ^ j2;
                if (l > i) {
                    bool up = ((i & k2) == 0);
                    unsigned ki = key[i], kl = key[l];
                    bool swp = up ? (ki > kl) : (ki < kl);
                    if (swp) {
                        key[i] = kl; key[l] = ki;
                        int t = idx[i]; idx[i] = idx[l]; idx[l] = t;
                    }
                }
            }
            __syncthreads();
        }
    }

    float* out = (side ? g_p2 : g_p1) + b * NPTS * 3;
    for (int k = tid; k < NPTS; k += NTHREADS) {
        int s = idx[k];
        out[3*k]   = p[3*s];
        out[3*k+1] = p[3*s+1];
        out[3*k+2] = p[3*s+2];
    }
    __syncthreads();

    if (tid < NCHUNK) {
        float lx = 1e30f, ly = 1e30f, lz = 1e30f;
        float hx = -1e30f, hy = -1e30f, hz = -1e30f;
        for (int k = 0; k < 64; k++) {
            int j = tid * 64 + k;
            float x = out[3*j], y = out[3*j+1], z = out[3*j+2];
            lx = fminf(lx, x); hx = fmaxf(hx, x);
            ly = fminf(ly, y); hy = fmaxf(hy, y);
            lz = fminf(lz, z); hz = fmaxf(hz, z);
        }
        float4* glo = side ? g_lo2 : g_lo1;
        float4* ghi = side ? g_hi2 : g_hi1;
        glo[b * NCHUNK + tid] = make_float4(lx, ly, lz, 0.0f);
        ghi[b * NCHUNK + tid] = make_float4(hx, hy, hz, 0.0f);
    }
}

// ---------- Warmup: rigorous two-pass half-step (emits row max) ----------
__global__ __launch_bounds__(NTHREADS, 1)
void sink_warm(int dir)
{
    __shared__ float4 sA[NPAIR];
    __shared__ float4 sB[NPAIR];

    const int b = blockIdx.y, tid = threadIdx.x;
    const float* rowPts = dir ? g_p2 : g_p1;
    const float* colPts = dir ? g_p1 : g_p2;
    const float* colPot = dir ? g_f  : g_g;
    float*       outPot = dir ? g_g  : g_f;
    float*       outM   = dir ? g_mg : g_mf;

    const float* cp = colPts + b * NPTS * 3;
    const float* gp = colPot + b * NPTS;
    for (int p = tid; p < NPAIR; p += NTHREADS) {
        int j = 2 * p;
        float a0 = cp[3*j],   a1 = cp[3*j+1], a2 = cp[3*j+2];
        float b0 = cp[3*j+3], b1 = cp[3*j+4], b2 = cp[3*j+5];
        float ha = (gp[j]   - (a0*a0 + a1*a1 + a2*a2)) * KLOG;
        float hb = (gp[j+1] - (b0*b0 + b1*b1 + b2*b2)) * KLOG;
        sA[p] = make_float4(a0, b0, a1, b1);
        sB[p] = make_float4(a2, b2, ha, hb);
    }
    __syncthreads();

    const int warp = tid >> 5, lane = tid & 31;
    const int row0 = blockIdx.x * ROWS_PER_CTA + warp * 8;
    const float* rp = rowPts + b * NPTS * 3;

    u64 X0b[8], X1b[8], X2b[8];
    float xx[8], m[8];
    #pragma unroll
    for (int r = 0; r < 8; r++) {
        int i = row0 + r;
        float x0 = rp[3*i], x1 = rp[3*i+1], x2 = rp[3*i+2];
        xx[r] = x0*x0 + x1*x1 + x2*x2;
        X0b[r] = pack2(2.0f*KLOG*x0, 2.0f*KLOG*x0);
        X1b[r] = pack2(2.0f*KLOG*x1, 2.0f*KLOG*x1);
        X2b[r] = pack2(2.0f*KLOG*x2, 2.0f*KLOG*x2);
        m[r]  = -1e30f;
    }

    unsigned int aA0 = (unsigned int)__cvta_generic_to_shared(sA) + lane * 16u;
    unsigned int aB0 = (unsigned int)__cvta_generic_to_shared(sB) + lane * 16u;

    {
        unsigned int aA = aA0, aB = aB0;
        #pragma unroll 2
        for (int it = 0; it < NPAIR / 32; it++) {
            u64 y0p, y1p, y2p, hp;
            asm("ld.shared.v2.b64 {%0, %1}, [%2];" : "=l"(y0p), "=l"(y1p) : "r"(aA));
            asm("ld.shared.v2.b64 {%0, %1}, [%2];" : "=l"(y2p), "=l"(hp)  : "r"(aB));
            #pragma unroll
            for (int r = 0; r < 8; r++) {
                u64 w = fma2(X0b[r], y0p, fma2(X1b[r], y1p, fma2(X2b[r], y2p, hp)));
                float wl, wh; unpack2(w, wl, wh);
                m[r] = fmaxf(m[r], fmaxf(wl, wh));
            }
            aA += 512u; aB += 512u;
        }
    }

    u64 mnegb[8], Sp[8];
    #pragma unroll
    for (int r = 0; r < 8; r++) {
        #pragma unroll
        for (int o = 16; o; o >>= 1)
            m[r] = fmaxf(m[r], __shfl_xor_sync(0xffffffffu, m[r], o));
        mnegb[r] = pack2(-m[r], -m[r]);
        Sp[r] = 0ull;
    }

    {
        unsigned int aA = aA0, aB = aB0;
        #pragma unroll 2
        for (int it = 0; it < NPAIR / 32; it++) {
            u64 y0p, y1p, y2p, hp;
            asm("ld.shared.v2.b64 {%0, %1}, [%2];" : "=l"(y0p), "=l"(y1p) : "r"(aA));
            asm("ld.shared.v2.b64 {%0, %1}, [%2];" : "=l"(y2p), "=l"(hp)  : "r"(aB));
            #pragma unroll
            for (int r = 0; r < 8; r++) {
                u64 w = fma2(X0b[r], y0p, fma2(X1b[r], y1p, fma2(X2b[r], y2p, hp)));
                u64 t = add2(w, mnegb[r]);
                float tl, th; unpack2(t, tl, th);
                Sp[r] = add2(Sp[r], pack2(ex2f(tl), ex2f(th)));
            }
            aA += 512u; aB += 512u;
        }
    }

    float S[8];
    #pragma unroll
    for (int r = 0; r < 8; r++) {
        float sl, sh; unpack2(Sp[r], sl, sh);
        S[r] = sl + sh;
        #pragma unroll
        for (int o = 16; o; o >>= 1)
            S[r] += __shfl_xor_sync(0xffffffffu, S[r], o);
    }
    if (lane == 0) {
        #pragma unroll
        for (int r = 0; r < 8; r++) {
            outPot[b * NPTS + row0 + r] = ACONST - EPSLN2 * (m[r] + __log2f(S[r])) + xx[r];
            outM[b * NPTS + row0 + r]   = m[r];
        }
    }
}

// ---------- Persistent fast phase: 97 half-steps, resident tables, f16x2 exp ----------
__device__ __forceinline__ void half_step(
    unsigned sAb, unsigned sBb, const float2* __restrict__ yk,
    const float4* __restrict__ sLo, const float4* __restrict__ sHi,
    float* __restrict__ sGm,
    const float* __restrict__ colPot, float* __restrict__ outPot,
    const float* __restrict__ rowPts, int b, int row0, float* mp)
{
    const int tid = threadIdx.x, warp = tid >> 5, lane = tid & 31;

    // h update: one pair per thread; warp w covers exactly chunk w.
    {
        float2 g2 = __ldcg((const float2*)(colPot + b * NPTS + 2 * tid));
        float2 y = yk[tid];
        float ha = fmaf(g2.x, KLOG, -y.x);
        float hb = fmaf(g2.y, KLOG, -y.y);
        asm volatile("st.shared.v2.f32 [%0], {%1,%2};"
                     :: "r"(sBb + (unsigned)tid * 16u + 8u), "f"(ha), "f"(hb));
        float gm = fmaxf(g2.x, g2.y);
        #pragma unroll
        for (int o = 16; o; o >>= 1)
            gm = fmaxf(gm, __shfl_xor_sync(0xffffffffu, gm, o));
        if (lane == 0) sGm[warp] = gm;
    }
    __syncthreads();

    const float* rp = rowPts + b * NPTS * 3;
    u64 X0b[4], X1b[4], X2b[4], negMb[4];
    unsigned Sh[4];
    float S32[4], xx[4];
    #pragma unroll
    for (int r = 0; r < 4; r++) {
        int i = row0 + r;
        float x0 = rp[3*i], x1 = rp[3*i+1], x2 = rp[3*i+2];
        xx[r] = x0*x0 + x1*x1 + x2*x2;
        X0b[r] = pack2(2.0f*KLOG*x0, 2.0f*KLOG*x0);
        X1b[r] = pack2(2.0f*KLOG*x1, 2.0f*KLOG*x1);
        X2b[r] = pack2(2.0f*KLOG*x2, 2.0f*KLOG*x2);
        negMb[r] = pack2(-mp[r], -mp[r]);
        Sh[r] = 0u;
        S32[r] = 0.0f;
    }

    // Chunk mask: lane c bounds chunk c for this warp's 4 rows.
    unsigned mask;
    {
        float4 lo = sLo[lane], hi = sHi[lane];
        float gm = sGm[lane];
        bool act = false;
        #pragma unroll
        for (int r = 0; r < 4; r++) {
            float X0s, X1s, X2s, d;
            unpack2(X0b[r], X0s, d);
            unpack2(X1b[r], X1s, d);
            unpack2(X2b[r], X2s, d);
            float x0 = X0s * INV2K, x1 = X1s * INV2K, x2 = X2s * INV2K;
            float dx = fmaxf(fmaxf(lo.x - x0, x0 - hi.x), 0.0f);
            float dy = fmaxf(fmaxf(lo.y - x1, x1 - hi.y), 0.0f);
            float dz = fmaxf(fmaxf(lo.z - x2, x2 - hi.z), 0.0f);
            float d2 = dx*dx + dy*dy + dz*dz;
            float ub = KLOG * (gm + xx[r] - d2) - mp[r];
            act |= (ub > SKIP_THR);
        }
        mask = __ballot_sync(0xffffffffu, act);
    }

    unsigned aA = sAb + (unsigned)lane * 16u;
    unsigned aB = sBb + (unsigned)lane * 16u;
    for (int it = 0; it < NCHUNK; it++) {
        if (mask & (1u << it)) {
            u64 y0p, y1p, y2p, hp;
            asm("ld.shared.v2.b64 {%0, %1}, [%2];" : "=l"(y0p), "=l"(y1p) : "r"(aA));
            asm("ld.shared.v2.b64 {%0, %1}, [%2];" : "=l"(y2p), "=l"(hp)  : "r"(aB));
            #pragma unroll
            for (int r = 0; r < 4; r++) {
                u64 hpr = add2(hp, negMb[r]);
                u64 w = fma2(X0b[r], y0p, fma2(X1b[r], y1p, fma2(X2b[r], y2p, hpr)));
                float wl, wh; unpack2(w, wl, wh);
                unsigned hx, e;
                asm("cvt.rn.f16x2.f32 %0, %1, %2;" : "=r"(hx) : "f"(wh), "f"(wl));
                asm("ex2.approx.f16x2 %0, %1;" : "=r"(e) : "r"(hx));
                asm("add.rn.f16x2 %0, %1, %2;" : "=r"(Sh[r]) : "r"(Sh[r]), "r"(e));
            }
        }
        if ((it & 7) == 7) {
            // flush packed fp16 partials into fp32 accumulators
            #pragma unroll
            for (int r = 0; r < 4; r++) {
                __half2 h = *reinterpret_cast<__half2*>(&Sh[r]);
                S32[r] += __low2float(h) + __high2float(h);
                Sh[r] = 0u;
            }
        }
        aA += 512u; aB += 512u;
    }

    #pragma unroll
    for (int r = 0; r < 4; r++) {
        float S = S32[r];
        #pragma unroll
        for (int o = 16; o; o >>= 1)
            S += __shfl_xor_sync(0xffffffffu, S, o);
        float l2S = __log2f(fmaxf(S, 1e-38f));
        float f = ACONST - EPSLN2 * (mp[r] + l2S) + xx[r];
        if (lane == 0) outPot[b * NPTS + row0 + r] = f;
        mp[r] += l2S;   // safe over-estimate of new row max (all lanes identical)
    }
}

__global__ __launch_bounds__(PTHREADS, 1)
void sink_persist()
{
    extern __shared__ char smemraw[];
    float4* sA2 = (float4*)smemraw;
    float4* sB2 = sA2 + NPAIR;
    float4* sA1 = sB2 + NPAIR;
    float4* sB1 = sA1 + NPAIR;
    float2* yk2 = (float2*)(sB1 + NPAIR);
    float2* yk1 = yk2 + NPAIR;
    float4* sBox = (float4*)(yk1 + NPAIR);   // [lo2|hi2|lo1|hi1] x 32
    float*  sGm  = (float*)(sBox + 128);

    const int b = blockIdx.y, tid = threadIdx.x;
    const int warp = tid >> 5;

    if (tid < 32) {
        sBox[tid]      = g_lo2[b * NCHUNK + tid];
        sBox[32 + tid] = g_hi2[b * NCHUNK + tid];
        sBox[64 + tid] = g_lo1[b * NCHUNK + tid];
        sBox[96 + tid] = g_hi1[b * NCHUNK + tid];
    }
    // Build static point tables (one pair per thread).
    {
        int j = 2 * tid;
        const float* c2 = g_p2 + b * NPTS * 3;
        float a0 = c2[3*j],   a1 = c2[3*j+1], a2 = c2[3*j+2];
        float b0 = c2[3*j+3], b1 = c2[3*j+4], b2 = c2[3*j+5];
        sA2[tid] = make_float4(a0, b0, a1, b1);
        sB2[tid] = make_float4(a2, b2, 0.0f, 0.0f);
        yk2[tid] = make_float2((a0*a0 + a1*a1 + a2*a2) * KLOG,
                               (b0*b0 + b1*b1 + b2*b2) * KLOG);
        const float* c1 = g_p1 + b * NPTS * 3;
        float c_0 = c1[3*j],   c_1 = c1[3*j+1], c_2 = c1[3*j+2];
        float d_0 = c1[3*j+3], d_1 = c1[3*j+4], d_2 = c1[3*j+5];
        sA1[tid] = make_float4(c_0, d_0, c_1, d_1);
        sB1[tid] = make_float4(c_2, d_2, 0.0f, 0.0f);
        yk1[tid] = make_float2((c_0*c_0 + c_1*c_1 + c_2*c_2) * KLOG,
                               (d_0*d_0 + d_1*d_1 + d_2*d_2) * KLOG);
    }
    __syncthreads();

    const int row0 = blockIdx.x * 128 + warp * 4;
    float mpf[4], mpg[4];
    #pragma unroll
    for (int r = 0; r < 4; r++) {
        mpf[r] = g_mf[b * NPTS + row0 + r];
        mpg[r] = g_mg[b * NPTS + row0 + r];
    }

    const unsigned a2b = (unsigned)__cvta_generic_to_shared(sA2);
    const unsigned b2b = (unsigned)__cvta_generic_to_shared(sB2);
    const unsigned a1b = (unsigned)__cvta_generic_to_shared(sA1);
    const unsigned b1b = (unsigned)__cvta_generic_to_shared(sB1);

    #pragma unroll 1
    for (int s = 0; s < PSTEPS; s++) {
        if ((s & 1) == 0)
            half_step(a2b, b2b, yk2, sBox, sBox + 32, sGm, g_g, g_f, g_p1, b, row0, mpf);
        else
            half_step(a1b, b1b, yk1, sBox + 64, sBox + 96, sGm, g_f, g_g, g_p2, b, row0, mpg);
        if (s != PSTEPS - 1) grid_bar();
    }
}

// dist_i = N * sum_j 2^(K(f_i+g_j-C_ij)) * C_ij ; coarse chunk skip
__global__ __launch_bounds__(NTHREADS, 1)
void dist_kernel()
{
    __shared__ float4 sCol[NPTS];
    __shared__ float  sYY[NPTS];
    __shared__ float  sGm[64];
    __shared__ float4 sLo[NCHUNK], sHi[NCHUNK];
    __shared__ float  wsum[16];

    const int b = blockIdx.y, tid = threadIdx.x;
    const int warp = tid >> 5, lane = tid & 31;

    if (tid < NCHUNK) {
        sLo[tid] = g_lo2[b * NCHUNK + tid];
        sHi[tid] = g_hi2[b * NCHUNK + tid];
    }

    const float* cp = g_p2 + b * NPTS * 3;
    #pragma unroll
    for (int k = 0; k < 4; k++) {
        int j = tid + k * NTHREADS;
        float gv = g_g[b * NPTS + j];
        float y0 = cp[3*j], y1 = cp[3*j+1], y2 = cp[3*j+2];
        float yy = y0*y0 + y1*y1 + y2*y2;
        sYY[j] = yy;
        sCol[j] = make_float4(y0, y1, y2, (gv - yy) * KLOG);
        float gm = gv;
        #pragma unroll
        for (int o = 16; o; o >>= 1)
            gm = fmaxf(gm, __shfl_xor_sync(0xffffffffu, gm, o));
        if (lane == 0) sGm[warp + k * 16] = gm;
    }
    __syncthreads();

    const int row0 = blockIdx.x * ROWS_PER_CTA + warp * 8;
    const float* rp = g_p1 + b * NPTS * 3;

    float X0[8], X1[8], X2[8], xx[8], cr[8], acc[8], fK[8];
    #pragma unroll
    for (int r = 0; r < 8; r++) {
        int i = row0 + r;
        float x0 = rp[3*i], x1 = rp[3*i+1], x2 = rp[3*i+2];
        xx[r] = x0*x0 + x1*x1 + x2*x2;
        X0[r] = 2.0f*KLOG*x0;
        X1[r] = 2.0f*KLOG*x1;
        X2[r] = 2.0f*KLOG*x2;
        float fv = g_f[b * NPTS + i];
        fK[r] = fv * KLOG;
        cr[r] = (fv - xx[r]) * KLOG;
        acc[r] = 0.0f;
    }

    unsigned mask;
    {
        float4 lo = sLo[lane], hi = sHi[lane];
        float gm = fmaxf(sGm[2 * lane], sGm[2 * lane + 1]);
        bool act = false;
        #pragma unroll
        for (int r = 0; r < 8; r++) {
            float x0 = X0[r] * INV2K, x1 = X1[r] * INV2K, x2 = X2[r] * INV2K;
            float dx = fmaxf(fmaxf(lo.x - x0, x0 - hi.x), 0.0f);
            float dy = fmaxf(fmaxf(lo.y - x1, x1 - hi.y), 0.0f);
            float dz = fmaxf(fmaxf(lo.z - x2, x2 - hi.z), 0.0f);
            float d2 = dx*dx + dy*dy + dz*dz;
            float ub = fK[r] + KLOG * (gm - d2);
            act |= (ub > SKIP_THR);
        }
        mask = __ballot_sync(0xffffffffu, act);
    }

    for (int c = 0; c < NCHUNK; c++) {
        if (!(mask & (1u << c))) continue;
        #pragma unroll
        for (int s = 0; s < 2; s++) {
            int j = c * 64 + s * 32 + lane;
            float4 col = sCol[j];
            float yy = sYY[j];
            #pragma unroll
            for (int r = 0; r < 8; r++) {
                float t = fmaf(X0[r], col.x, fmaf(X1[r], col.y, X2[r] * col.z));
                float p = ex2f(t + col.w + cr[r]);
                float C = fmaf(-EPSLN2, t, xx[r] + yy);
                acc[r] = fmaf(p, C, acc[r]);
            }
        }
    }
    #pragma unroll
    for (int r = 0; r < 8; r++) {
        #pragma unroll
        for (int o = 16; o; o >>= 1)
            acc[r] += __shfl_xor_sync(0xffffffffu, acc[r], o);
    }

    if (lane == 0) {
        float s = 0.0f;
        #pragma unroll
        for (int r = 0; r < 8; r++)
            s += sqrtf(fmaxf(acc[r] * (float)NPTS, 0.0f));
        wsum[warp] = s;
    }
    __syncthreads();
    if (tid == 0) {
        float s = 0.0f;
        #pragma unroll
        for (int w = 0; w < 16; w++) s += wsum[w];
        g_partial[b * CHUNKS + blockIdx.x] = s;
    }
}

__global__ void final_kernel(float* __restrict__ out) {
    __shared__ float s[BB * CHUNKS];
    int tid = threadIdx.x;
    s[tid] = g_partial[tid];
    __syncthreads();
    for (int o = (BB * CHUNKS) / 2; o; o >>= 1) {
        if (tid < o) s[tid] += s[tid + o];
        __syncthreads();
    }
    if (tid == 0) out[0] = s[0] * (1.0f / (BB * NPTS));
}

extern "C" void kernel_launch(void* const* d_in, const int* in_sizes, int n_in,
                              void* d_out, int out_size)
{
    const float* pcs1 = (const float*)d_in[0];
    const float* pcs2 = (const float*)d_in[1];
    float* out = (float*)d_out;

    static int smem_set = 0;
    const int PSMEM = 4 * NPAIR * 16 + 2 * NPAIR * 8 + 128 * 16 + 32 * 4;
    if (!smem_set) {
        cudaFuncSetAttribute(sink_persist, cudaFuncAttributeMaxDynamicSharedMemorySize, PSMEM);
        smem_set = 1;
    }

    init_kernel<<<(BB * NPTS + NTHREADS - 1) / NTHREADS, NTHREADS>>>();
    sort_kernel<<<BB, NTHREADS>>>(pcs1, 0);
    sort_kernel<<<BB, NTHREADS>>>(pcs2, 1);

    dim3 gridW(CHUNKS, BB);
    for (int it = 0; it < 2; it++) {
        sink_warm<<<gridW, NTHREADS>>>(0);
        sink_warm<<<gridW, NTHREADS>>>(1);
    }

    sink_persist<<<dim3(CHUNKS, BB), PTHREADS, PSMEM>>>();

    dist_kernel<<<gridW, NTHREADS>>>();
    final_kernel<<<1, BB * CHUNKS>>>(out);
}

// round 16
// speedup vs baseline: 1.1461x; 1.1461x over previous
#include <cuda_runtime.h>
#include <math.h>

#define BB 8
#define NPTS 2048
#define NPAIR 1024
#define NTHREADS 512
#define ROWS_PER_CTA 128          // dist: 16 warps * 8 rows
#define CHUNKS 16                 // dist grid.x
#define NCHUNK 32                 // j-chunks of 64 points

// persistent kernel
#define PTHREADS 1024             // 32 warps * 4 rows = 128 rows/CTA
#define NCTA 128                  // 16 x-chunks * 8 batches, all resident
#define PSTEPS 101                // 50*(f,g) + final f

// eps = 0.005
#define KLOG 288.53900817779268f          // log2(e)/eps
#define INV2K 0.0017328679513998633f      // 1/(2*KLOG)
#define EPSLN2 0.0034657359027997266f     // eps*ln2
#define ACONST (-0.038123094930796993f)   // eps*log(1/N)
#define SKIP_THR (-25.0f)

typedef unsigned long long u64;

__device__ __forceinline__ float ex2f(float x) {
    float r;
    asm("ex2.approx.ftz.f32 %0, %1;" : "=f"(r) : "f"(x));
    return r;
}
__device__ __forceinline__ u64 pack2(float lo, float hi) {
    u64 r; asm("mov.b64 %0, {%1, %2};" : "=l"(r) : "f"(lo), "f"(hi)); return r;
}
__device__ __forceinline__ void unpack2(u64 v, float& lo, float& hi) {
    asm("mov.b64 {%0, %1}, %2;" : "=f"(lo), "=f"(hi) : "l"(v));
}
__device__ __forceinline__ u64 fma2(u64 a, u64 b, u64 c) {
    u64 r; asm("fma.rn.f32x2 %0, %1, %2, %3;" : "=l"(r) : "l"(a), "l"(b), "l"(c)); return r;
}
__device__ __forceinline__ u64 add2(u64 a, u64 b) {
    u64 r; asm("add.rn.f32x2 %0, %1, %2;" : "=l"(r) : "l"(a), "l"(b)); return r;
}

// Persistent scratch
__device__ float  g_p1[BB * NPTS * 3];
__device__ float  g_p2[BB * NPTS * 3];
__device__ float4 g_lo1[BB * NCHUNK], g_hi1[BB * NCHUNK];
__device__ float4 g_lo2[BB * NCHUNK], g_hi2[BB * NCHUNK];
__device__ float  g_f[BB * NPTS];
__device__ float  g_g[BB * NPTS];
__device__ float  g_partial[BB * CHUNKS];

// grid barrier state (generation counter: no reset needed across graph replays)
__device__ int      g_bar_cnt;
__device__ unsigned g_bar_gen;

__device__ __forceinline__ void grid_bar() {
    __syncthreads();
    if (threadIdx.x == 0) {
        __threadfence();   // release: make this CTA's writes visible
        unsigned gen;
        asm volatile("ld.volatile.global.u32 %0, [%1];" : "=r"(gen) : "l"(&g_bar_gen));
        if (atomicAdd(&g_bar_cnt, 1) == NCTA - 1) {
            asm volatile("st.volatile.global.u32 [%0], %1;" :: "l"(&g_bar_cnt), "r"(0));
            __threadfence();
            atomicAdd(&g_bar_gen, 1u);
        } else {
            unsigned cur;
            do {
                asm volatile("ld.volatile.global.u32 %0, [%1];" : "=r"(cur) : "l"(&g_bar_gen));
            } while (cur == gen);
        }
        __threadfence();   // acquire: see other CTAs' writes
    }
    __syncthreads();
}

__global__ void init_kernel() {
    int i = blockIdx.x * blockDim.x + threadIdx.x;
    if (i < BB * NPTS) g_g[i] = 0.0f;
}

__device__ __forceinline__ unsigned expand_bits(unsigned v) {
    v &= 0x3FFu;
    v = (v | (v << 16)) & 0x030000FFu;
    v = (v | (v << 8))  & 0x0300F00Fu;
    v = (v | (v << 4))  & 0x030C30C3u;
    v = (v | (v << 2))  & 0x09249249u;
    return v;
}

// One CTA per batch: Morton bitonic sort + per-chunk AABB.
__global__ __launch_bounds__(NTHREADS, 1)
void sort_kernel(const float* __restrict__ pts, int side)
{
    __shared__ unsigned key[NPTS];
    __shared__ int      idx[NPTS];
    const int b = blockIdx.x, tid = threadIdx.x;
    const float* p = pts + b * NPTS * 3;

    for (int j = tid; j < NPTS; j += NTHREADS) {
        float x = p[3*j], y = p[3*j+1], z = p[3*j+2];
        unsigned qx = (unsigned)fminf(fmaxf(x * 1024.0f, 0.0f), 1023.0f);
        unsigned qy = (unsigned)fminf(fmaxf(y * 1024.0f, 0.0f), 1023.0f);
        unsigned qz = (unsigned)fminf(fmaxf(z * 1024.0f, 0.0f), 1023.0f);
        key[j] = expand_bits(qx) | (expand_bits(qy) << 1) | (expand_bits(qz) << 2);
        idx[j] = j;
    }
    __syncthreads();

    for (int k2 = 2; k2 <= NPTS; k2 <<= 1) {
        for (int j2 = k2 >> 1; j2 > 0; j2 >>= 1) {
            for (int i = tid; i < NPTS; i += NTHREADS) {
                int l = i ^ j2;
                if (l > i) {
                    bool up = ((i & k2) == 0);
                    unsigned ki = key[i], kl = key[l];
                    bool swp = up ? (ki > kl) : (ki < kl);
                    if (swp) {
                        key[i] = kl; key[l] = ki;
                        int t = idx[i]; idx[i] = idx[l]; idx[l] = t;
                    }
                }
            }
            __syncthreads();
        }
    }

    float* out = (side ? g_p2 : g_p1) + b * NPTS * 3;
    for (int k = tid; k < NPTS; k += NTHREADS) {
        int s = idx[k];
        out[3*k]   = p[3*s];
        out[3*k+1] = p[3*s+1];
        out[3*k+2] = p[3*s+2];
    }
    __syncthreads();

    if (tid < NCHUNK) {
        float lx = 1e30f, ly = 1e30f, lz = 1e30f;
        float hx = -1e30f, hy = -1e30f, hz = -1e30f;
        for (int k = 0; k < 64; k++) {
            int j = tid * 64 + k;
            float x = out[3*j], y = out[3*j+1], z = out[3*j+2];
            lx = fminf(lx, x); hx = fmaxf(hx, x);
            ly = fminf(ly, y); hy = fmaxf(hy, y);
            lz = fminf(lz, z); hz = fmaxf(hz, z);
        }
        float4* glo = side ? g_lo2 : g_lo1;
        float4* ghi = side ? g_hi2 : g_hi1;
        glo[b * NCHUNK + tid] = make_float4(lx, ly, lz, 0.0f);
        ghi[b * NCHUNK + tid] = make_float4(hx, hy, hz, 0.0f);
    }
}

// ---------- Persistent phase: all 101 half-steps, resident tables ----------
// mp is a running OVER-ESTIMATE of the row max (exactness preserved: it is
// only a range shift). Initialized analytically as K*||x||^2.
__device__ __forceinline__ void half_step(
    unsigned sAb, unsigned sBb, const float2* __restrict__ yk,
    const float4* __restrict__ sLo, const float4* __restrict__ sHi,
    float* __restrict__ sGm,
    const float* __restrict__ colPot, float* __restrict__ outPot,
    const float* __restrict__ rowPts, int b, int row0, float* mp)
{
    const int tid = threadIdx.x, warp = tid >> 5, lane = tid & 31;

    // h update: one pair per thread; warp w covers exactly chunk w.
    {
        float2 g2 = __ldcg((const float2*)(colPot + b * NPTS + 2 * tid));
        float2 y = yk[tid];
        float ha = fmaf(g2.x, KLOG, -y.x);
        float hb = fmaf(g2.y, KLOG, -y.y);
        asm volatile("st.shared.v2.f32 [%0], {%1,%2};"
                     :: "r"(sBb + (unsigned)tid * 16u + 8u), "f"(ha), "f"(hb));
        float gm = fmaxf(g2.x, g2.y);
        #pragma unroll
        for (int o = 16; o; o >>= 1)
            gm = fmaxf(gm, __shfl_xor_sync(0xffffffffu, gm, o));
        if (lane == 0) sGm[warp] = gm;
    }
    __syncthreads();

    const float* rp = rowPts + b * NPTS * 3;
    u64 X0b[4], X1b[4], X2b[4], negMb[4], Sp[4];
    float xx[4];
    #pragma unroll
    for (int r = 0; r < 4; r++) {
        int i = row0 + r;
        float x0 = rp[3*i], x1 = rp[3*i+1], x2 = rp[3*i+2];
        xx[r] = x0*x0 + x1*x1 + x2*x2;
        X0b[r] = pack2(2.0f*KLOG*x0, 2.0f*KLOG*x0);
        X1b[r] = pack2(2.0f*KLOG*x1, 2.0f*KLOG*x1);
        X2b[r] = pack2(2.0f*KLOG*x2, 2.0f*KLOG*x2);
        negMb[r] = pack2(-mp[r], -mp[r]);
        Sp[r] = 0ull;
    }

    // Chunk mask: lane c bounds chunk c for this warp's 4 rows.
    unsigned mask;
    {
        float4 lo = sLo[lane], hi = sHi[lane];
        float gm = sGm[lane];
        bool act = false;
        #pragma unroll
        for (int r = 0; r < 4; r++) {
            float X0s, X1s, X2s, d;
            unpack2(X0b[r], X0s, d);
            unpack2(X1b[r], X1s, d);
            unpack2(X2b[r], X2s, d);
            float x0 = X0s * INV2K, x1 = X1s * INV2K, x2 = X2s * INV2K;
            float dx = fmaxf(fmaxf(lo.x - x0, x0 - hi.x), 0.0f);
            float dy = fmaxf(fmaxf(lo.y - x1, x1 - hi.y), 0.0f);
            float dz = fmaxf(fmaxf(lo.z - x2, x2 - hi.z), 0.0f);
            float d2 = dx*dx + dy*dy + dz*dz;
            float ub = KLOG * (gm + xx[r] - d2) - mp[r];
            act |= (ub > SKIP_THR);
        }
        mask = __ballot_sync(0xffffffffu, act);
    }

    unsigned aA = sAb + (unsigned)lane * 16u;
    unsigned aB = sBb + (unsigned)lane * 16u;
    for (int it = 0; it < NCHUNK; it++) {
        if (mask & (1u << it)) {
            u64 y0p, y1p, y2p, hp;
            asm("ld.shared.v2.b64 {%0, %1}, [%2];" : "=l"(y0p), "=l"(y1p) : "r"(aA));
            asm("ld.shared.v2.b64 {%0, %1}, [%2];" : "=l"(y2p), "=l"(hp)  : "r"(aB));
            #pragma unroll
            for (int r = 0; r < 4; r++) {
                u64 hpr = add2(hp, negMb[r]);
                u64 w = fma2(X0b[r], y0p, fma2(X1b[r], y1p, fma2(X2b[r], y2p, hpr)));
                float wl, wh; unpack2(w, wl, wh);
                Sp[r] = add2(Sp[r], pack2(ex2f(wl), ex2f(wh)));
            }
        }
        aA += 512u; aB += 512u;
    }

    #pragma unroll
    for (int r = 0; r < 4; r++) {
        float sl, sh; unpack2(Sp[r], sl, sh);
        float S = sl + sh;
        #pragma unroll
        for (int o = 16; o; o >>= 1)
            S += __shfl_xor_sync(0xffffffffu, S, o);
        float l2S = __log2f(fmaxf(S, 1e-38f));
        float f = ACONST - EPSLN2 * (mp[r] + l2S) + xx[r];
        if (lane == 0) outPot[b * NPTS + row0 + r] = f;
        mp[r] += l2S;   // safe over-estimate of new row max (all lanes identical)
    }
}

__global__ __launch_bounds__(PTHREADS, 1)
void sink_persist()
{
    extern __shared__ char smemraw[];
    float4* sA2 = (float4*)smemraw;
    float4* sB2 = sA2 + NPAIR;
    float4* sA1 = sB2 + NPAIR;
    float4* sB1 = sA1 + NPAIR;
    float2* yk2 = (float2*)(sB1 + NPAIR);
    float2* yk1 = yk2 + NPAIR;
    float4* sBox = (float4*)(yk1 + NPAIR);   // [lo2|hi2|lo1|hi1] x 32
    float*  sGm  = (float*)(sBox + 128);

    const int b = blockIdx.y, tid = threadIdx.x;
    const int warp = tid >> 5;

    if (tid < 32) {
        sBox[tid]      = g_lo2[b * NCHUNK + tid];
        sBox[32 + tid] = g_hi2[b * NCHUNK + tid];
        sBox[64 + tid] = g_lo1[b * NCHUNK + tid];
        sBox[96 + tid] = g_hi1[b * NCHUNK + tid];
    }
    // Build static point tables (one pair per thread).
    {
        int j = 2 * tid;
        const float* c2 = g_p2 + b * NPTS * 3;
        float a0 = c2[3*j],   a1 = c2[3*j+1], a2 = c2[3*j+2];
        float b0 = c2[3*j+3], b1 = c2[3*j+4], b2 = c2[3*j+5];
        sA2[tid] = make_float4(a0, b0, a1, b1);
        sB2[tid] = make_float4(a2, b2, 0.0f, 0.0f);
        yk2[tid] = make_float2((a0*a0 + a1*a1 + a2*a2) * KLOG,
                               (b0*b0 + b1*b1 + b2*b2) * KLOG);
        const float* c1 = g_p1 + b * NPTS * 3;
        float c_0 = c1[3*j],   c_1 = c1[3*j+1], c_2 = c1[3*j+2];
        float d_0 = c1[3*j+3], d_1 = c1[3*j+4], d_2 = c1[3*j+5];
        sA1[tid] = make_float4(c_0, d_0, c_1, d_1);
        sB1[tid] = make_float4(c_2, d_2, 0.0f, 0.0f);
        yk1[tid] = make_float2((c_0*c_0 + c_1*c_1 + c_2*c_2) * KLOG,
                               (d_0*d_0 + d_1*d_1 + d_2*d_2) * KLOG);
    }
    __syncthreads();

    // Stride-interleaved row-group assignment: each CTA samples the whole
    // Morton range -> balanced active-chunk counts across CTAs.
    const int row0 = (warp * 16 + blockIdx.x) * 4;

    // Analytic initial carried max: mp0 = K*||x||^2 >= true first-step max.
    float mpf[4], mpg[4];
    {
        const float* r1 = g_p1 + b * NPTS * 3;
        const float* r2 = g_p2 + b * NPTS * 3;
        #pragma unroll
        for (int r = 0; r < 4; r++) {
            int i = row0 + r;
            float a0 = r1[3*i], a1 = r1[3*i+1], a2 = r1[3*i+2];
            mpf[r] = (a0*a0 + a1*a1 + a2*a2) * KLOG;
            float b0 = r2[3*i], b1 = r2[3*i+1], b2 = r2[3*i+2];
            mpg[r] = (b0*b0 + b1*b1 + b2*b2) * KLOG;
        }
    }

    const unsigned a2b = (unsigned)__cvta_generic_to_shared(sA2);
    const unsigned b2b = (unsigned)__cvta_generic_to_shared(sB2);
    const unsigned a1b = (unsigned)__cvta_generic_to_shared(sA1);
    const unsigned b1b = (unsigned)__cvta_generic_to_shared(sB1);

    #pragma unroll 1
    for (int s = 0; s < PSTEPS; s++) {
        if ((s & 1) == 0)
            half_step(a2b, b2b, yk2, sBox, sBox + 32, sGm, g_g, g_f, g_p1, b, row0, mpf);
        else
            half_step(a1b, b1b, yk1, sBox + 64, sBox + 96, sGm, g_f, g_g, g_p2, b, row0, mpg);
        if (s != PSTEPS - 1) grid_bar();
    }
}

// dist_i = N * sum_j 2^(K(f_i+g_j-C_ij)) * C_ij ; coarse chunk skip
__global__ __launch_bounds__(NTHREADS, 1)
void dist_kernel()
{
    __shared__ float4 sCol[NPTS];
    __shared__ float  sYY[NPTS];
    __shared__ float  sGm[64];
    __shared__ float4 sLo[NCHUNK], sHi[NCHUNK];
    __shared__ float  wsum[16];

    const int b = blockIdx.y, tid = threadIdx.x;
    const int warp = tid >> 5, lane = tid & 31;

    if (tid < NCHUNK) {
        sLo[tid] = g_lo2[b * NCHUNK + tid];
        sHi[tid] = g_hi2[b * NCHUNK + tid];
    }

    const float* cp = g_p2 + b * NPTS * 3;
    #pragma unroll
    for (int k = 0; k < 4; k++) {
        int j = tid + k * NTHREADS;
        float gv = g_g[b * NPTS + j];
        float y0 = cp[3*j], y1 = cp[3*j+1], y2 = cp[3*j+2];
        float yy = y0*y0 + y1*y1 + y2*y2;
        sYY[j] = yy;
        sCol[j] = make_float4(y0, y1, y2, (gv - yy) * KLOG);
        float gm = gv;
        #pragma unroll
        for (int o = 16; o; o >>= 1)
            gm = fmaxf(gm, __shfl_xor_sync(0xffffffffu, gm, o));
        if (lane == 0) sGm[warp + k * 16] = gm;
    }
    __syncthreads();

    const int row0 = blockIdx.x * ROWS_PER_CTA + warp * 8;
    const float* rp = g_p1 + b * NPTS * 3;

    float X0[8], X1[8], X2[8], xx[8], cr[8], acc[8], fK[8];
    #pragma unroll
    for (int r = 0; r < 8; r++) {
        int i = row0 + r;
        float x0 = rp[3*i], x1 = rp[3*i+1], x2 = rp[3*i+2];
        xx[r] = x0*x0 + x1*x1 + x2*x2;
        X0[r] = 2.0f*KLOG*x0;
        X1[r] = 2.0f*KLOG*x1;
        X2[r] = 2.0f*KLOG*x2;
        float fv = g_f[b * NPTS + i];
        fK[r] = fv * KLOG;
        cr[r] = (fv - xx[r]) * KLOG;
        acc[r] = 0.0f;
    }

    unsigned mask;
    {
        float4 lo = sLo[lane], hi = sHi[lane];
        float gm = fmaxf(sGm[2 * lane], sGm[2 * lane + 1]);
        bool act = false;
        #pragma unroll
        for (int r = 0; r < 8; r++) {
            float x0 = X0[r] * INV2K, x1 = X1[r] * INV2K, x2 = X2[r] * INV2K;
            float dx = fmaxf(fmaxf(lo.x - x0, x0 - hi.x), 0.0f);
            float dy = fmaxf(fmaxf(lo.y - x1, x1 - hi.y), 0.0f);
            float dz = fmaxf(fmaxf(lo.z - x2, x2 - hi.z), 0.0f);
            float d2 = dx*dx + dy*dy + dz*dz;
            float ub = fK[r] + KLOG * (gm - d2);
            act |= (ub > SKIP_THR);
        }
        mask = __ballot_sync(0xffffffffu, act);
    }

    for (int c = 0; c < NCHUNK; c++) {
        if (!(mask & (1u << c))) continue;
        #pragma unroll
        for (int s = 0; s < 2; s++) {
            int j = c * 64 + s * 32 + lane;
            float4 col = sCol[j];
            float yy = sYY[j];
            #pragma unroll
            for (int r = 0; r < 8; r++) {
                float t = fmaf(X0[r], col.x, fmaf(X1[r], col.y, X2[r] * col.z));
                float p = ex2f(t + col.w + cr[r]);
                float C = fmaf(-EPSLN2, t, xx[r] + yy);
                acc[r] = fmaf(p, C, acc[r]);
            }
        }
    }
    #pragma unroll
    for (int r = 0; r < 8; r++) {
        #pragma unroll
        for (int o = 16; o; o >>= 1)
            acc[r] += __shfl_xor_sync(0xffffffffu, acc[r], o);
    }

    if (lane == 0) {
        float s = 0.0f;
        #pragma unroll
        for (int r = 0; r < 8; r++)
            s += sqrtf(fmaxf(acc[r] * (float)NPTS, 0.0f));
        wsum[warp] = s;
    }
    __syncthreads();
    if (tid == 0) {
        float s = 0.0f;
        #pragma unroll
        for (int w = 0; w < 16; w++) s += wsum[w];
        g_partial[b * CHUNKS + blockIdx.x] = s;
    }
}

__global__ void final_kernel(float* __restrict__ out) {
    __shared__ float s[BB * CHUNKS];
    int tid = threadIdx.x;
    s[tid] = g_partial[tid];
    __syncthreads();
    for (int o = (BB * CHUNKS) / 2; o; o >>= 1) {
        if (tid < o) s[tid] += s[tid + o];
        __syncthreads();
    }
    if (tid == 0) out[0] = s[0] * (1.0f / (BB * NPTS));
}

extern "C" void kernel_launch(void* const* d_in, const int* in_sizes, int n_in,
                              void* d_out, int out_size)
{
    const float* pcs1 = (const float*)d_in[0];
    const float* pcs2 = (const float*)d_in[1];
    float* out = (float*)d_out;

    static int smem_set = 0;
    const int PSMEM = 4 * NPAIR * 16 + 2 * NPAIR * 8 + 128 * 16 + 32 * 4;
    if (!smem_set) {
        cudaFuncSetAttribute(sink_persist, cudaFuncAttributeMaxDynamicSharedMemorySize, PSMEM);
        smem_set = 1;
    }

    init_kernel<<<(BB * NPTS + NTHREADS - 1) / NTHREADS, NTHREADS>>>();
    sort_kernel<<<BB, NTHREADS>>>(pcs1, 0);
    sort_kernel<<<BB, NTHREADS>>>(pcs2, 1);

    sink_persist<<<dim3(CHUNKS, BB), PTHREADS, PSMEM>>>();

    dist_kernel<<<dim3(CHUNKS, BB), NTHREADS>>>();
    final_kernel<<<1, BB * CHUNKS>>>(out);
}